// round 15
// baseline (speedup 1.0000x reference)
#include <cuda_runtime.h>
#include <math.h>

// Scratch for the fallback path only.
__device__ float g_weights[4096 * 80];

// ===========================================================================
// FUSED kernel (fast path: dim=256, cols=65, H=W=64, hidden=16).
// Grid = N/4 CTAs x 256 threads, launch_bounds(256,3) -> 3 CTAs/SM, 1.35 waves.
//
// Phase 1 (GEMM): weights for 4 queries into smem (k-split over 8 warps,
//   partial reduce) — scratch lives inside the bins region (reused later).
// Phase 2 (tables): per (box,unit) float4 {e0=w0*tx+b1, w1, alpha=w2*s, 1/s},
//   tiny-slope substitution for s~0 (validated round 9).
// Phase 3 (pixels, 2 passes of 256 tasks): task = (box, row y, half h).
//   Breakpoint scatter: per unit, UNCONDITIONAL masked RMW into the thread-
//   private bins column (out-of-window -> zero-add into slot 0; no branches).
//   Prefix sweep over 32 px: A+=dA, B+=dB, out = fma(A, xg, B).
//   ~6 SMSP-cyc/px instead of the 64-cyc fp32 FMA wall.
// ===========================================================================
#define SM_BINS 0        // 32 slots x 256 threads x float2 = 16384 floats (64KB)
                         //   (also GEMM scratch: sqT 1024 + partials 2112)
#define SM_SW   16384    // weights: 4 x 68 = 272 floats
#define SM_TAB  16656    // tables: 64 float4 = 256 floats
#define SM_TOT  16912    // 67648 bytes

__global__ void __launch_bounds__(256, 3)
posmlp_bins32_kernel(const float* __restrict__ pos,
                     const float* __restrict__ q,
                     const float* __restrict__ Wg,
                     const float* __restrict__ bg,
                     float* __restrict__ out) {
    extern __shared__ float sm[];
    __shared__ float4 spos[4];

    const int n0  = blockIdx.x * 4;
    const int tid = threadIdx.x;
    const int w   = tid >> 5;
    const int l   = tid & 31;

    // ---- Phase 1: GEMM (scratch inside bins region) ----
    #pragma unroll
    for (int i = tid; i < 1024; i += 256) {
        const int nn = i >> 8;
        const int d  = i & 255;
        sm[SM_BINS + d * 4 + nn] = q[(size_t)n0 * 256 + i];
    }
    if (tid < 4)
        spos[tid] = *reinterpret_cast<const float4*>(&pos[(size_t)(n0 + tid) * 4]);
    __syncthreads();

    {
        const int d0 = w * 32;
        float2 acc[4];
        #pragma unroll
        for (int nn = 0; nn < 4; nn++) acc[nn] = make_float2(0.f, 0.f);
        float acc64[4] = {0.f, 0.f, 0.f, 0.f};

        #pragma unroll
        for (int db = 0; db < 32; db += 8) {
            float wpx[8], wpy[8], w64[8];
            #pragma unroll
            for (int j = 0; j < 8; j++) {
                const size_t base = (size_t)(d0 + db + j) * 65;
                wpx[j] = Wg[base + 2 * l];
                wpy[j] = Wg[base + 2 * l + 1];
                w64[j] = Wg[base + 64];
            }
            #pragma unroll
            for (int j = 0; j < 8; j++) {
                const int d = d0 + db + j;
                const float4 qa = *reinterpret_cast<const float4*>(&sm[SM_BINS + d * 4]);
                const float qv[4] = {qa.x, qa.y, qa.z, qa.w};
                #pragma unroll
                for (int nn = 0; nn < 4; nn++) {
                    acc[nn].x = fmaf(qv[nn], wpx[j], acc[nn].x);
                    acc[nn].y = fmaf(qv[nn], wpy[j], acc[nn].y);
                }
                if (l == 0) {
                    #pragma unroll
                    for (int nn = 0; nn < 4; nn++)
                        acc64[nn] = fmaf(qv[nn], w64[j], acc64[nn]);
                }
            }
        }
        __syncthreads();   // sqT reads done before partials overwrite region

        #pragma unroll
        for (int nn = 0; nn < 4; nn++) {
            *reinterpret_cast<float2*>(&sm[SM_BINS + 1024 + (w * 4 + nn) * 66 + 2 * l]) = acc[nn];
        }
        if (l == 0) {
            #pragma unroll
            for (int nn = 0; nn < 4; nn++)
                sm[SM_BINS + 1024 + (w * 4 + nn) * 66 + 64] = acc64[nn];
        }
        __syncthreads();

        for (int o = tid; o < 260; o += 256) {
            const int nn = o / 65;
            const int c  = o - nn * 65;
            float s = 0.f;
            #pragma unroll
            for (int w8 = 0; w8 < 8; w8++)
                s += sm[SM_BINS + 1024 + (w8 * 4 + nn) * 66 + c];
            sm[SM_SW + nn * 68 + c] = s + bg[c];
        }
    }
    __syncthreads();

    // ---- Phase 2: unit tables {e0, w1, alpha=w2*s, inv=1/s} ----
    if (tid < 64) {
        const int nn = tid >> 4;
        const int k  = tid & 15;
        const float* wv = &sm[SM_SW + nn * 68];
        const float4 p = spos[nn];
        const float inv_bw = 1.0f / p.z;
        const float sx = inv_bw * (1.0f / 64.0f);
        const float tx = (0.5f * (1.0f / 64.0f) - p.x) * inv_bw;

        const float w0 = wv[k];
        const float w2 = wv[48 + k];
        float s = w0 * sx;
        float alpha, inv;
        if (fabsf(s) < 1e-18f) {
            const float sgn = (s >= 0.f) ? 1.0f : -1.0f;
            alpha = w2 * (sgn * 1e-30f);
            inv   = sgn * 1e30f;
        } else {
            alpha = w2 * s;
            inv   = __fdividef(1.0f, s);
        }
        reinterpret_cast<float4*>(&sm[SM_TAB])[nn * 16 + k] =
            make_float4(fmaf(w0, tx, wv[32 + k]), wv[16 + k], alpha, inv);
    }

    // ---- Phase 3: two passes of 256 tasks ----
    float2* bins = reinterpret_cast<float2*>(&sm[SM_BINS]);
    const int h  = (tid >> 6) & 1;
    const int y  = tid & 63;
    const float Lf    = 32.0f * (float)h;
    const float yc    = ((float)y + 0.5f) * (1.0f / 64.0f);

    #pragma unroll
    for (int pass = 0; pass < 2; pass++) {
        const int nn = pass * 2 + (tid >> 7);

        // Zero bins cooperatively (16 float4 per thread).
        __syncthreads();
        {
            float4* b4 = reinterpret_cast<float4*>(&sm[SM_BINS]);
            #pragma unroll
            for (int i = 0; i < 16; i++)
                b4[tid + i * 256] = make_float4(0.f, 0.f, 0.f, 0.f);
        }
        __syncthreads();

        const float4 p = spos[nn];
        const float rel_y = (yc - p.y) * (1.0f / p.w);
        const float4* tabn = reinterpret_cast<const float4*>(&sm[SM_TAB]) + nn * 16;

        float A0 = 0.f;
        float B0 = sm[SM_SW + nn * 68 + 64];

        // Scatter: straight-line, masked RMW (no branches).
        #pragma unroll
        for (int k = 0; k < 16; k++) {
            const float4 T = tabn[k];            // e0, w1, alpha, inv
            const float c    = fmaf(rel_y, T.y, T.x);
            const float u    = c * T.w;          // = -breakpoint (global x)
            const float beta = T.z * u;          // = w2 * c
            float v = u + Lf;
            v = fminf(fmaxf(v, -32.5f), 0.5f);
            int bl = -__float2int_rd(v);         // 0..33
            bl = min(bl, 32);

            const bool  neg  = (T.w < 0.f);
            const bool  add0 = neg ? (bl > 0) : (bl == 0);
            A0 += add0 ? T.z  : 0.f;
            B0 += add0 ? beta : 0.f;

            const bool  inw  = (unsigned)(bl - 1) < 31u;   // 1..31
            const int   slot = inw ? bl : 0;
            const float sgn  = neg ? -1.f : 1.f;
            const float va   = inw ? sgn * T.z  : 0.f;
            const float vb   = inw ? sgn * beta : 0.f;
            float2 d = bins[slot * 256 + tid];
            d.x += va;
            d.y += vb;
            bins[slot * 256 + tid] = d;
        }

        // Prefix sweep over 32 px; float4 stores.
        float A = A0, B = B0;
        float xg = Lf;
        float* orow = out + (((size_t)(n0 + nn) * 64 + y) * 64 + 32 * h);

        #pragma unroll
        for (int xi = 0; xi < 32; xi += 4) {
            float4 res;
            float* rp = &res.x;
            #pragma unroll
            for (int j = 0; j < 4; j++) {
                const float2 d = bins[(xi + j) * 256 + tid];
                A += d.x;
                B += d.y;
                rp[j] = fmaf(A, xg, B);
                xg += 1.0f;
            }
            *reinterpret_cast<float4*>(orow + xi) = res;
        }
    }
}

// ===========================================================================
// Fallback path (other shapes).
// ===========================================================================
__global__ void posmlp_gemm_kernel(const float* __restrict__ q,
                                   const float* __restrict__ Wg,
                                   const float* __restrict__ bg,
                                   float* __restrict__ w_out,
                                   int dim, int cols) {
    extern __shared__ float sqf[];
    const int n = blockIdx.x;
    const float* qr = q + (size_t)n * dim;
    for (int d = threadIdx.x; d < dim; d += blockDim.x) sqf[d] = qr[d];
    __syncthreads();
    for (int j = threadIdx.x; j < cols; j += blockDim.x) {
        float acc = bg[j];
        #pragma unroll 8
        for (int d = 0; d < dim; d++) {
            acc = fmaf(sqf[d], Wg[(size_t)d * cols + j], acc);
        }
        w_out[(size_t)n * cols + j] = acc;
    }
}

__global__ void posmlp_generic_kernel(const float* __restrict__ pos,
                                      const float* __restrict__ wts,
                                      float* __restrict__ out,
                                      int H, int W, int h, int cols) {
    const int n = blockIdx.x;
    const float* w = wts + (size_t)n * cols;
    const float cx = pos[(size_t)n * 4 + 0];
    const float cy = pos[(size_t)n * 4 + 1];
    const float bw = pos[(size_t)n * 4 + 2];
    const float bh = pos[(size_t)n * 4 + 3];
    const float b2 = w[4 * h];
    const int total = H * W;
    for (int idx = threadIdx.x; idx < total; idx += blockDim.x) {
        const int yy = idx / W;
        const int xx = idx - yy * W;
        const float rel_x = (((float)xx + 0.5f) / (float)W - cx) / bw;
        const float rel_y = (((float)yy + 0.5f) / (float)H - cy) / bh;
        float acc = b2;
        for (int k = 0; k < h; k++) {
            float pre = fmaf(rel_x, w[k], fmaf(rel_y, w[h + k], w[2 * h + k]));
            acc = fmaf(fmaxf(pre, 0.0f), w[3 * h + k], acc);
        }
        out[(size_t)n * total + idx] = acc;
    }
}

extern "C" void kernel_launch(void* const* d_in, const int* in_sizes, int n_in,
                              void* d_out, int out_size) {
    const float* pos = (const float*)d_in[0];
    const float* q   = (const float*)d_in[1];
    const float* Wg  = (const float*)d_in[2];
    const float* bg  = (const float*)d_in[3];
    float* out = (float*)d_out;

    const int N    = in_sizes[0] / 4;          // rows of pos
    const int dim  = in_sizes[1] / N;          // query dim
    const int cols = in_sizes[3];              // 4*h + 1
    const int HW   = out_size / N;
    const int H    = (int)(sqrt((double)HW) + 0.5);
    const int h    = (cols - 1) / 4;

    if (H == 64 && h == 16 && cols == 65 && dim == 256 && (N % 4) == 0) {
        const int smem_bytes = SM_TOT * sizeof(float);  // ~66 KB
        cudaFuncSetAttribute(posmlp_bins32_kernel,
                             cudaFuncAttributeMaxDynamicSharedMemorySize, smem_bytes);
        posmlp_bins32_kernel<<<N / 4, 256, smem_bytes>>>(pos, q, Wg, bg, out);
    } else {
        float* w_scratch;
        cudaGetSymbolAddress((void**)&w_scratch, g_weights);
        posmlp_gemm_kernel<<<N, 256, dim * sizeof(float)>>>(q, Wg, bg, w_scratch, dim, cols);
        posmlp_generic_kernel<<<N, 256>>>(pos, w_scratch, out, H, H, h, cols);
    }
}

// round 16
// speedup vs baseline: 1.1220x; 1.1220x over previous
#include <cuda_runtime.h>
#include <math.h>

typedef unsigned long long u64;

// Scratch for the fallback path only.
__device__ float g_weights[4096 * 80];

// ---------------------------------------------------------------------------
// f32x2 packed helpers (sm_100+)
// ---------------------------------------------------------------------------
__device__ __forceinline__ u64 pack2(float lo, float hi) {
    u64 r;
    asm("mov.b64 %0, {%1, %2};" : "=l"(r) : "f"(lo), "f"(hi));
    return r;
}

__device__ __forceinline__ void unpack2(u64 v, float& lo, float& hi) {
    asm("mov.b64 {%0, %1}, %2;" : "=f"(lo), "=f"(hi) : "l"(v));
}

// acc = |x2*w10 + ay| * w2h
__device__ __forceinline__ void fma2_abs_init(u64& acc, u64 x2, u64 w10,
                                              u64 ay, u64 w2h) {
    asm("{\n\t"
        ".reg .b32 lo, hi;\n\t"
        ".reg .b64 p, r;\n\t"
        "fma.rn.f32x2 p, %1, %2, %3;\n\t"
        "mov.b64 {lo, hi}, p;\n\t"
        "abs.f32 lo, lo;\n\t"
        "abs.f32 hi, hi;\n\t"
        "mov.b64 r, {lo, hi};\n\t"
        "mul.rn.f32x2 %0, r, %4;\n\t"
        "}"
        : "=l"(acc)
        : "l"(x2), "l"(w10), "l"(ay), "l"(w2h));
}

// acc += |x2*w10 + ay| * w2h
__device__ __forceinline__ void fma2_abs_acc(u64& acc, u64 x2, u64 w10,
                                             u64 ay, u64 w2h) {
    asm("{\n\t"
        ".reg .b32 lo, hi;\n\t"
        ".reg .b64 p, r;\n\t"
        "fma.rn.f32x2 p, %1, %2, %3;\n\t"
        "mov.b64 {lo, hi}, p;\n\t"
        "abs.f32 lo, lo;\n\t"
        "abs.f32 hi, hi;\n\t"
        "mov.b64 r, {lo, hi};\n\t"
        "fma.rn.f32x2 %0, r, %4, %0;\n\t"
        "}"
        : "+l"(acc)
        : "l"(x2), "l"(w10), "l"(ay), "l"(w2h));
}

// ===========================================================================
// FUSED kernel (fast path, dim=256, cols=65, H=W=64, hidden=16).
// Grid = N/4 CTAs x 256 threads, launch_bounds(256,4): 4 boxes per CTA,
// 600 CTAs at 4 CTAs/SM = 1.014 waves (592 slots) — near-perfect balance,
// and staggered CTA starts overlap GEMM (phase 1) with pixels (phase 3).
// ILP-4 chains (32 fewer live regs than ILP-8); 32 warps/SM supply the TLP.
// Tables (w10/w2h/w1/b1 packed pairs) in smem; only ayp per-thread regs.
// ===========================================================================
#define FSQ   0                    // sqT: 256 x 4              = 1024 floats
#define FPR   1024                 // partials: 8*4 x 66        = 2112 floats
#define FSW   3136                 // weights: 4 x 68           = 272 floats
#define FTAB  3408                 // 4 u64 tables x 32 entries = 256 floats
#define FLA   3664                 // LA per box                = 4 floats
#define FTOT  3672                 // ~14.7 KB -> occ 4 fits (58.8 KB/SM)

__global__ void __launch_bounds__(256, 4)
posmlp_fused4_kernel(const float* __restrict__ pos,
                     const float* __restrict__ q,
                     const float* __restrict__ Wg,
                     const float* __restrict__ bg,
                     float* __restrict__ out) {
    extern __shared__ float sm[];
    __shared__ float4 spos[4];

    const int n0  = blockIdx.x * 4;
    const int tid = threadIdx.x;
    const int w   = tid >> 5;
    const int l   = tid & 31;

    // ---- Phase 1: GEMM into smem ----
    #pragma unroll
    for (int i = tid; i < 1024; i += 256) {
        const int nn = i >> 8;
        const int d  = i & 255;
        sm[FSQ + d * 4 + nn] = q[(size_t)n0 * 256 + i];
    }
    if (tid < 4)
        spos[tid] = *reinterpret_cast<const float4*>(&pos[(size_t)(n0 + tid) * 4]);
    __syncthreads();

    {
        const int d0 = w * 32;
        float2 acc[4];
        #pragma unroll
        for (int nn = 0; nn < 4; nn++) acc[nn] = make_float2(0.f, 0.f);
        float acc64[4] = {0.f, 0.f, 0.f, 0.f};

        #pragma unroll
        for (int db = 0; db < 32; db += 8) {
            float wpx[8], wpy[8], w64[8];
            #pragma unroll
            for (int j = 0; j < 8; j++) {
                const size_t base = (size_t)(d0 + db + j) * 65;
                wpx[j] = Wg[base + 2 * l];
                wpy[j] = Wg[base + 2 * l + 1];
                w64[j] = Wg[base + 64];
            }
            #pragma unroll
            for (int j = 0; j < 8; j++) {
                const int d = d0 + db + j;
                const float4 qa = *reinterpret_cast<const float4*>(&sm[FSQ + d * 4]);
                const float qv[4] = {qa.x, qa.y, qa.z, qa.w};
                #pragma unroll
                for (int nn = 0; nn < 4; nn++) {
                    acc[nn].x = fmaf(qv[nn], wpx[j], acc[nn].x);
                    acc[nn].y = fmaf(qv[nn], wpy[j], acc[nn].y);
                }
                if (l == 0) {
                    #pragma unroll
                    for (int nn = 0; nn < 4; nn++)
                        acc64[nn] = fmaf(qv[nn], w64[j], acc64[nn]);
                }
            }
        }

        #pragma unroll
        for (int nn = 0; nn < 4; nn++) {
            *reinterpret_cast<float2*>(&sm[FPR + (w * 4 + nn) * 66 + 2 * l]) = acc[nn];
        }
        if (l == 0) {
            #pragma unroll
            for (int nn = 0; nn < 4; nn++) sm[FPR + (w * 4 + nn) * 66 + 64] = acc64[nn];
        }
        __syncthreads();

        for (int o = tid; o < 260; o += 256) {
            const int nn = o / 65;
            const int c  = o - nn * 65;
            float s = 0.f;
            #pragma unroll
            for (int w8 = 0; w8 < 8; w8++) s += sm[FPR + (w8 * 4 + nn) * 66 + c];
            sm[FSW + nn * 68 + c] = s + bg[c];
        }
    }
    __syncthreads();

    // ---- Build packed u64 tables + per-box LA ----
    {
        u64* stw10 = reinterpret_cast<u64*>(&sm[FTAB]);
        u64* stw2h = stw10 + 32;
        u64* stw1  = stw10 + 64;
        u64* stb1  = stw10 + 96;
        if (tid < 32) {
            const int nn = tid >> 3;
            const int k2 = tid & 7;
            const int k  = 2 * k2;
            const float* wv = &sm[FSW + nn * 68];
            const float h0 = 0.5f * wv[48 + k];
            const float h1 = 0.5f * wv[48 + k + 1];
            stw10[nn * 8 + k2] = pack2(wv[k], wv[k + 1]);
            stw2h[nn * 8 + k2] = pack2(h0, h1);
            stw1[nn * 8 + k2]  = pack2(wv[16 + k], wv[16 + k + 1]);
            stb1[nn * 8 + k2]  = pack2(wv[32 + k], wv[32 + k + 1]);
        } else if (tid < 36) {
            const int nn = tid - 32;
            const float* wv = &sm[FSW + nn * 68];
            float LA = 0.f;
            #pragma unroll
            for (int k = 0; k < 16; k++)
                LA = fmaf(wv[k], 0.5f * wv[48 + k], LA);
            sm[FLA + nn] = LA;
        }
    }
    __syncthreads();

    // ---- Phase 3: pixel evaluation (ILP-4, 4 batches of 4 px) ----
    const u64* stw10 = reinterpret_cast<const u64*>(&sm[FTAB]);
    const u64* stw2h = stw10 + 32;
    const u64* stw1  = stw10 + 64;
    const u64* stb1  = stw10 + 96;

    const int y  = tid >> 2;
    const int x0 = (tid & 3) * 16;
    const float yc = ((float)y + 0.5f) * (1.0f / 64.0f);

    for (int nn = 0; nn < 4; nn++) {
        const float4 p = spos[nn];
        const float inv_bw = 1.0f / p.z;
        const float inv_bh = 1.0f / p.w;
        const float rel_y = (yc - p.y) * inv_bh;

        // Per-thread ayp + LB (table reads are broadcast LDS.64)
        u64 ayp[8];
        float LB = 0.f;
        #pragma unroll
        for (int k2 = 0; k2 < 8; k2++) {
            float w1a, w1b, b1a, b1b, h0, h1;
            unpack2(stw1[nn * 8 + k2], w1a, w1b);
            unpack2(stb1[nn * 8 + k2], b1a, b1b);
            unpack2(stw2h[nn * 8 + k2], h0, h1);
            const float a0 = fmaf(rel_y, w1a, b1a);
            const float a1 = fmaf(rel_y, w1b, b1b);
            ayp[k2] = pack2(a0, a1);
            LB = fmaf(a0, h0, LB);
            LB = fmaf(a1, h1, LB);
        }
        const float LA   = sm[FLA + nn];
        const float LBb2 = LB + sm[FSW + nn * 68 + 64];

        const float sx = inv_bw * (1.0f / 64.0f);
        const float tx = (0.5f * (1.0f / 64.0f) - p.x) * inv_bw;

        float* orow = out + (((size_t)(n0 + nn) * 64 + y) * 64 + x0);

        #pragma unroll
        for (int batch = 0; batch < 4; batch++) {
            const int xb = x0 + batch * 4;

            u64 x2[4];
            float rx[4];
            #pragma unroll
            for (int j = 0; j < 4; j++) {
                rx[j] = fmaf((float)(xb + j), sx, tx);
                x2[j] = pack2(rx[j], rx[j]);
            }

            u64 acc[4];
            {
                const u64 w10 = stw10[nn * 8];
                const u64 w2h = stw2h[nn * 8];
                #pragma unroll
                for (int j = 0; j < 4; j++)
                    fma2_abs_init(acc[j], x2[j], w10, ayp[0], w2h);
            }
            #pragma unroll
            for (int k2 = 1; k2 < 8; k2++) {
                const u64 w10 = stw10[nn * 8 + k2];
                const u64 w2h = stw2h[nn * 8 + k2];
                #pragma unroll
                for (int j = 0; j < 4; j++)
                    fma2_abs_acc(acc[j], x2[j], w10, ayp[k2], w2h);
            }

            float4 res;
            float* rp = &res.x;
            #pragma unroll
            for (int j = 0; j < 4; j++) {
                float lo, hi;
                unpack2(acc[j], lo, hi);
                rp[j] = (lo + hi) + fmaf(rx[j], LA, LBb2);
            }
            *reinterpret_cast<float4*>(orow + batch * 4) = res;
        }
    }
}

// ===========================================================================
// Fallback path (other shapes).
// ===========================================================================
__global__ void posmlp_gemm_kernel(const float* __restrict__ q,
                                   const float* __restrict__ Wg,
                                   const float* __restrict__ bg,
                                   float* __restrict__ w_out,
                                   int dim, int cols) {
    extern __shared__ float sqf[];
    const int n = blockIdx.x;
    const float* qr = q + (size_t)n * dim;
    for (int d = threadIdx.x; d < dim; d += blockDim.x) sqf[d] = qr[d];
    __syncthreads();
    for (int j = threadIdx.x; j < cols; j += blockDim.x) {
        float acc = bg[j];
        #pragma unroll 8
        for (int d = 0; d < dim; d++) {
            acc = fmaf(sqf[d], Wg[(size_t)d * cols + j], acc);
        }
        w_out[(size_t)n * cols + j] = acc;
    }
}

__global__ void posmlp_generic_kernel(const float* __restrict__ pos,
                                      const float* __restrict__ wts,
                                      float* __restrict__ out,
                                      int H, int W, int h, int cols) {
    const int n = blockIdx.x;
    const float* w = wts + (size_t)n * cols;
    const float cx = pos[(size_t)n * 4 + 0];
    const float cy = pos[(size_t)n * 4 + 1];
    const float bw = pos[(size_t)n * 4 + 2];
    const float bh = pos[(size_t)n * 4 + 3];
    const float b2 = w[4 * h];
    const int total = H * W;
    for (int idx = threadIdx.x; idx < total; idx += blockDim.x) {
        const int yy = idx / W;
        const int xx = idx - yy * W;
        const float rel_x = (((float)xx + 0.5f) / (float)W - cx) / bw;
        const float rel_y = (((float)yy + 0.5f) / (float)H - cy) / bh;
        float acc = b2;
        for (int k = 0; k < h; k++) {
            float pre = fmaf(rel_x, w[k], fmaf(rel_y, w[h + k], w[2 * h + k]));
            acc = fmaf(fmaxf(pre, 0.0f), w[3 * h + k], acc);
        }
        out[(size_t)n * total + idx] = acc;
    }
}

extern "C" void kernel_launch(void* const* d_in, const int* in_sizes, int n_in,
                              void* d_out, int out_size) {
    const float* pos = (const float*)d_in[0];
    const float* q   = (const float*)d_in[1];
    const float* Wg  = (const float*)d_in[2];
    const float* bg  = (const float*)d_in[3];
    float* out = (float*)d_out;

    const int N    = in_sizes[0] / 4;          // rows of pos
    const int dim  = in_sizes[1] / N;          // query dim
    const int cols = in_sizes[3];              // 4*h + 1
    const int HW   = out_size / N;
    const int H    = (int)(sqrt((double)HW) + 0.5);
    const int h    = (cols - 1) / 4;

    if (H == 64 && h == 16 && cols == 65 && dim == 256 && (N % 4) == 0) {
        const int smem_bytes = FTOT * sizeof(float);  // ~14.7 KB
        cudaFuncSetAttribute(posmlp_fused4_kernel,
                             cudaFuncAttributeMaxDynamicSharedMemorySize, smem_bytes);
        posmlp_fused4_kernel<<<N / 4, 256, smem_bytes>>>(pos, q, Wg, bg, out);
    } else {
        float* w_scratch;
        cudaGetSymbolAddress((void**)&w_scratch, g_weights);
        posmlp_gemm_kernel<<<N, 256, dim * sizeof(float)>>>(q, Wg, bg, w_scratch, dim, cols);
        posmlp_generic_kernel<<<N, 256>>>(pos, w_scratch, out, H, H, h, cols);
    }
}

// round 17
// speedup vs baseline: 1.3040x; 1.1622x over previous
#include <cuda_runtime.h>
#include <math.h>

typedef unsigned long long u64;

// Scratch for the fallback path only.
__device__ float g_weights[4096 * 80];

// ---------------------------------------------------------------------------
// f32x2 packed helpers (sm_100+)
// ---------------------------------------------------------------------------
__device__ __forceinline__ u64 pack2(float lo, float hi) {
    u64 r;
    asm("mov.b64 %0, {%1, %2};" : "=l"(r) : "f"(lo), "f"(hi));
    return r;
}

__device__ __forceinline__ void unpack2(u64 v, float& lo, float& hi) {
    asm("mov.b64 {%0, %1}, %2;" : "=f"(lo), "=f"(hi) : "l"(v));
}

// acc = |x2*w10 + ay| * w2h
__device__ __forceinline__ void fma2_abs_init(u64& acc, u64 x2, u64 w10,
                                              u64 ay, u64 w2h) {
    asm("{\n\t"
        ".reg .b32 lo, hi;\n\t"
        ".reg .b64 p, r;\n\t"
        "fma.rn.f32x2 p, %1, %2, %3;\n\t"
        "mov.b64 {lo, hi}, p;\n\t"
        "abs.f32 lo, lo;\n\t"
        "abs.f32 hi, hi;\n\t"
        "mov.b64 r, {lo, hi};\n\t"
        "mul.rn.f32x2 %0, r, %4;\n\t"
        "}"
        : "=l"(acc)
        : "l"(x2), "l"(w10), "l"(ay), "l"(w2h));
}

// acc += |x2*w10 + ay| * w2h
__device__ __forceinline__ void fma2_abs_acc(u64& acc, u64 x2, u64 w10,
                                             u64 ay, u64 w2h) {
    asm("{\n\t"
        ".reg .b32 lo, hi;\n\t"
        ".reg .b64 p, r;\n\t"
        "fma.rn.f32x2 p, %1, %2, %3;\n\t"
        "mov.b64 {lo, hi}, p;\n\t"
        "abs.f32 lo, lo;\n\t"
        "abs.f32 hi, hi;\n\t"
        "mov.b64 r, {lo, hi};\n\t"
        "fma.rn.f32x2 %0, r, %4, %0;\n\t"
        "}"
        : "+l"(acc)
        : "l"(x2), "l"(w10), "l"(ay), "l"(w2h));
}

// ===========================================================================
// FUSED kernel (fast path, dim=256, cols=65, H=W=64, hidden=16).
// Grid = N/6 = 400 CTAs x 256 threads, launch_bounds(256,3).
// 400 CTAs <= 444 slots -> SINGLE WAVE; worst SM carries 3 CTAs = 18 boxes
// vs 16.2 ideal (11% quantization — best integral split at occ 3).
// Phase 1: GEMM for 6 queries into smem (8-warp k-split, partial reduce).
// Phase 2: packed u64 weight tables in smem (broadcast LDS.64 in the loop).
// Phase 3: per box, FFMA2-abs inner loop (validated), ILP-8, float4 stores.
// ===========================================================================
#define FSQ   0                    // sqT: 256 x 6              = 1536 floats
#define FPR   1536                 // partials: 8*6 x 66        = 3168 floats
#define FSW   4704                 // weights: 6 x 68           = 408 floats
#define FTAB  5112                 // 4 u64 tables x 48 entries = 384 floats
#define FLA   5496                 // LA per box                = 6 floats
#define FTOT  5504                 // ~22 KB -> occ 3 fits easily

__global__ void __launch_bounds__(256, 3)
posmlp_fused6_kernel(const float* __restrict__ pos,
                     const float* __restrict__ q,
                     const float* __restrict__ Wg,
                     const float* __restrict__ bg,
                     float* __restrict__ out) {
    extern __shared__ float sm[];
    __shared__ float4 spos[6];

    const int n0  = blockIdx.x * 6;
    const int tid = threadIdx.x;
    const int w   = tid >> 5;
    const int l   = tid & 31;

    // ---- Phase 1: GEMM into smem ----
    #pragma unroll
    for (int i = tid; i < 1536; i += 256) {
        const int nn = i >> 8;
        const int d  = i & 255;
        sm[FSQ + d * 6 + nn] = q[(size_t)n0 * 256 + i];
    }
    if (tid < 6)
        spos[tid] = *reinterpret_cast<const float4*>(&pos[(size_t)(n0 + tid) * 4]);
    __syncthreads();

    {
        const int d0 = w * 32;
        float2 acc[6];
        #pragma unroll
        for (int nn = 0; nn < 6; nn++) acc[nn] = make_float2(0.f, 0.f);
        float acc64[6] = {0.f, 0.f, 0.f, 0.f, 0.f, 0.f};

        #pragma unroll
        for (int db = 0; db < 32; db += 8) {
            float wpx[8], wpy[8], w64[8];
            #pragma unroll
            for (int j = 0; j < 8; j++) {
                const size_t base = (size_t)(d0 + db + j) * 65;
                wpx[j] = Wg[base + 2 * l];
                wpy[j] = Wg[base + 2 * l + 1];
                w64[j] = Wg[base + 64];
            }
            #pragma unroll
            for (int j = 0; j < 8; j++) {
                const int d = d0 + db + j;
                const float2 qa = *reinterpret_cast<const float2*>(&sm[FSQ + d * 6 + 0]);
                const float2 qb = *reinterpret_cast<const float2*>(&sm[FSQ + d * 6 + 2]);
                const float2 qc = *reinterpret_cast<const float2*>(&sm[FSQ + d * 6 + 4]);
                const float qv[6] = {qa.x, qa.y, qb.x, qb.y, qc.x, qc.y};
                #pragma unroll
                for (int nn = 0; nn < 6; nn++) {
                    acc[nn].x = fmaf(qv[nn], wpx[j], acc[nn].x);
                    acc[nn].y = fmaf(qv[nn], wpy[j], acc[nn].y);
                }
                if (l == 0) {
                    #pragma unroll
                    for (int nn = 0; nn < 6; nn++)
                        acc64[nn] = fmaf(qv[nn], w64[j], acc64[nn]);
                }
            }
        }

        #pragma unroll
        for (int nn = 0; nn < 6; nn++) {
            *reinterpret_cast<float2*>(&sm[FPR + (w * 6 + nn) * 66 + 2 * l]) = acc[nn];
        }
        if (l == 0) {
            #pragma unroll
            for (int nn = 0; nn < 6; nn++) sm[FPR + (w * 6 + nn) * 66 + 64] = acc64[nn];
        }
        __syncthreads();

        for (int o = tid; o < 390; o += 256) {
            const int nn = o / 65;
            const int c  = o - nn * 65;
            float s = 0.f;
            #pragma unroll
            for (int w8 = 0; w8 < 8; w8++) s += sm[FPR + (w8 * 6 + nn) * 66 + c];
            sm[FSW + nn * 68 + c] = s + bg[c];
        }
    }
    __syncthreads();

    // ---- Phase 2: packed u64 tables + per-box LA ----
    {
        u64* stw10 = reinterpret_cast<u64*>(&sm[FTAB]);
        u64* stw2h = stw10 + 48;
        u64* stw1  = stw10 + 96;
        u64* stb1  = stw10 + 144;
        if (tid < 48) {
            const int nn = tid >> 3;
            const int k2 = tid & 7;
            const int k  = 2 * k2;
            const float* wv = &sm[FSW + nn * 68];
            const float h0 = 0.5f * wv[48 + k];
            const float h1 = 0.5f * wv[48 + k + 1];
            stw10[nn * 8 + k2] = pack2(wv[k], wv[k + 1]);
            stw2h[nn * 8 + k2] = pack2(h0, h1);
            stw1[nn * 8 + k2]  = pack2(wv[16 + k], wv[16 + k + 1]);
            stb1[nn * 8 + k2]  = pack2(wv[32 + k], wv[32 + k + 1]);
        } else if (tid < 54) {
            const int nn = tid - 48;
            const float* wv = &sm[FSW + nn * 68];
            float LA = 0.f;
            #pragma unroll
            for (int k = 0; k < 16; k++)
                LA = fmaf(wv[k], 0.5f * wv[48 + k], LA);
            sm[FLA + nn] = LA;
        }
    }
    __syncthreads();

    // ---- Phase 3: pixel evaluation (ILP-8, 2 batches of 8 px per box) ----
    const u64* stw10 = reinterpret_cast<const u64*>(&sm[FTAB]);
    const u64* stw2h = stw10 + 48;
    const u64* stw1  = stw10 + 96;
    const u64* stb1  = stw10 + 144;

    const int y  = tid >> 2;
    const int x0 = (tid & 3) * 16;
    const float yc = ((float)y + 0.5f) * (1.0f / 64.0f);

    for (int nn = 0; nn < 6; nn++) {
        const float4 p = spos[nn];
        const float inv_bw = 1.0f / p.z;
        const float inv_bh = 1.0f / p.w;
        const float rel_y = (yc - p.y) * inv_bh;

        // Per-thread ayp + LB (table reads are broadcast LDS.64)
        u64 ayp[8];
        float LB = 0.f;
        #pragma unroll
        for (int k2 = 0; k2 < 8; k2++) {
            float w1a, w1b, b1a, b1b, h0, h1;
            unpack2(stw1[nn * 8 + k2], w1a, w1b);
            unpack2(stb1[nn * 8 + k2], b1a, b1b);
            unpack2(stw2h[nn * 8 + k2], h0, h1);
            const float a0 = fmaf(rel_y, w1a, b1a);
            const float a1 = fmaf(rel_y, w1b, b1b);
            ayp[k2] = pack2(a0, a1);
            LB = fmaf(a0, h0, LB);
            LB = fmaf(a1, h1, LB);
        }
        const float LA   = sm[FLA + nn];
        const float LBb2 = LB + sm[FSW + nn * 68 + 64];

        const float sx = inv_bw * (1.0f / 64.0f);
        const float tx = (0.5f * (1.0f / 64.0f) - p.x) * inv_bw;

        float* orow = out + (((size_t)(n0 + nn) * 64 + y) * 64 + x0);

        #pragma unroll
        for (int batch = 0; batch < 2; batch++) {
            const int xb = x0 + batch * 8;

            u64 x2[8];
            float rx[8];
            #pragma unroll
            for (int j = 0; j < 8; j++) {
                rx[j] = fmaf((float)(xb + j), sx, tx);
                x2[j] = pack2(rx[j], rx[j]);
            }

            u64 acc[8];
            {
                const u64 w10 = stw10[nn * 8];
                const u64 w2h = stw2h[nn * 8];
                #pragma unroll
                for (int j = 0; j < 8; j++)
                    fma2_abs_init(acc[j], x2[j], w10, ayp[0], w2h);
            }
            #pragma unroll
            for (int k2 = 1; k2 < 8; k2++) {
                const u64 w10 = stw10[nn * 8 + k2];
                const u64 w2h = stw2h[nn * 8 + k2];
                #pragma unroll
                for (int j = 0; j < 8; j++)
                    fma2_abs_acc(acc[j], x2[j], w10, ayp[k2], w2h);
            }

            float res[8];
            #pragma unroll
            for (int j = 0; j < 8; j++) {
                float lo, hi;
                unpack2(acc[j], lo, hi);
                res[j] = (lo + hi) + fmaf(rx[j], LA, LBb2);
            }
            float4 v0 = make_float4(res[0], res[1], res[2], res[3]);
            float4 v1 = make_float4(res[4], res[5], res[6], res[7]);
            *reinterpret_cast<float4*>(orow + batch * 8)     = v0;
            *reinterpret_cast<float4*>(orow + batch * 8 + 4) = v1;
        }
    }
}

// ===========================================================================
// Fallback path (other shapes).
// ===========================================================================
__global__ void posmlp_gemm_kernel(const float* __restrict__ q,
                                   const float* __restrict__ Wg,
                                   const float* __restrict__ bg,
                                   float* __restrict__ w_out,
                                   int dim, int cols) {
    extern __shared__ float sqf[];
    const int n = blockIdx.x;
    const float* qr = q + (size_t)n * dim;
    for (int d = threadIdx.x; d < dim; d += blockDim.x) sqf[d] = qr[d];
    __syncthreads();
    for (int j = threadIdx.x; j < cols; j += blockDim.x) {
        float acc = bg[j];
        #pragma unroll 8
        for (int d = 0; d < dim; d++) {
            acc = fmaf(sqf[d], Wg[(size_t)d * cols + j], acc);
        }
        w_out[(size_t)n * cols + j] = acc;
    }
}

__global__ void posmlp_generic_kernel(const float* __restrict__ pos,
                                      const float* __restrict__ wts,
                                      float* __restrict__ out,
                                      int H, int W, int h, int cols) {
    const int n = blockIdx.x;
    const float* w = wts + (size_t)n * cols;
    const float cx = pos[(size_t)n * 4 + 0];
    const float cy = pos[(size_t)n * 4 + 1];
    const float bw = pos[(size_t)n * 4 + 2];
    const float bh = pos[(size_t)n * 4 + 3];
    const float b2 = w[4 * h];
    const int total = H * W;
    for (int idx = threadIdx.x; idx < total; idx += blockDim.x) {
        const int yy = idx / W;
        const int xx = idx - yy * W;
        const float rel_x = (((float)xx + 0.5f) / (float)W - cx) / bw;
        const float rel_y = (((float)yy + 0.5f) / (float)H - cy) / bh;
        float acc = b2;
        for (int k = 0; k < h; k++) {
            float pre = fmaf(rel_x, w[k], fmaf(rel_y, w[h + k], w[2 * h + k]));
            acc = fmaf(fmaxf(pre, 0.0f), w[3 * h + k], acc);
        }
        out[(size_t)n * total + idx] = acc;
    }
}

extern "C" void kernel_launch(void* const* d_in, const int* in_sizes, int n_in,
                              void* d_out, int out_size) {
    const float* pos = (const float*)d_in[0];
    const float* q   = (const float*)d_in[1];
    const float* Wg  = (const float*)d_in[2];
    const float* bg  = (const float*)d_in[3];
    float* out = (float*)d_out;

    const int N    = in_sizes[0] / 4;          // rows of pos
    const int dim  = in_sizes[1] / N;          // query dim
    const int cols = in_sizes[3];              // 4*h + 1
    const int HW   = out_size / N;
    const int H    = (int)(sqrt((double)HW) + 0.5);
    const int h    = (cols - 1) / 4;

    if (H == 64 && h == 16 && cols == 65 && dim == 256 && (N % 6) == 0) {
        const int smem_bytes = FTOT * sizeof(float);  // ~22 KB
        cudaFuncSetAttribute(posmlp_fused6_kernel,
                             cudaFuncAttributeMaxDynamicSharedMemorySize, smem_bytes);
        posmlp_fused6_kernel<<<N / 6, 256, smem_bytes>>>(pos, q, Wg, bg, out);
    } else {
        float* w_scratch;
        cudaGetSymbolAddress((void**)&w_scratch, g_weights);
        posmlp_gemm_kernel<<<N, 256, dim * sizeof(float)>>>(q, Wg, bg, w_scratch, dim, cols);
        posmlp_generic_kernel<<<N, 256>>>(pos, w_scratch, out, H, H, h, cols);
    }
}